// round 6
// baseline (speedup 1.0000x reference)
#include <cuda_runtime.h>
#include <cuda_bf16.h>
#include <cstdint>

#define E_EDGES   1048576
#define V_SEG     50000
#define V_PAD     50048
#define C_IN      128
#define C_MID     256
#define C_OUT     128
#define KTOT      384      // 3 x 128 split-K (hi*whi + lo*whi + hi*wlo)
#define NCHUNK    6        // KTOT / 64

// ---------------- device scratch ----------------
__device__ __align__(16) __nv_bfloat16 g_B1[C_MID * KTOT];   // [256][384] = [Whi|Whi|Wlo]
__device__ __align__(16) __nv_bfloat16 g_B3[C_OUT * KTOT];   // [128][384]
__device__ float g_Wt2v[C_MID * C_OUT];                      // W2v^T (256 x 128)
__device__ float g_zvmax[V_PAD * C_MID];
__device__ float g_zvertex[V_SEG * C_OUT];
// counting sort
__device__ unsigned g_count[V_PAD];
__device__ unsigned g_offset[V_PAD];
__device__ unsigned g_bsum[256];
__device__ unsigned g_btop[256];
__device__ int g_order[E_EDGES];   // sorted pos -> original edge
__device__ int g_svid[E_EDGES];    // vid in sorted order (non-decreasing)

// ---------------- helpers ----------------
__device__ __forceinline__ uint32_t smem_to_u32(const void* p) {
    uint32_t a;
    asm("{ .reg .u64 t; cvta.to.shared.u64 t, %1; cvt.u32.u64 %0, t; }" : "=r"(a) : "l"(p));
    return a;
}
#define SWZ(o) ((o) ^ (((o) >> 3) & 0x70))

#define CP_ASYNC16(dst, src) \
    asm volatile("cp.async.cg.shared.global [%0], [%1], 16;" :: "r"(dst), "l"(src))
#define CP_COMMIT() asm volatile("cp.async.commit_group;" ::: "memory")
#define CP_WAIT1()  asm volatile("cp.async.wait_group 1;" ::: "memory")
#define CP_WAIT0()  asm volatile("cp.async.wait_group 0;" ::: "memory")

#define LDSM_X4(r0, r1, r2, r3, addr) \
    asm volatile("ldmatrix.sync.aligned.m8n8.x4.shared.b16 {%0,%1,%2,%3}, [%4];" \
                 : "=r"(r0), "=r"(r1), "=r"(r2), "=r"(r3) : "r"(addr))

#define MMA16816(d, a, b) \
    asm volatile("mma.sync.aligned.m16n8k16.row.col.f32.bf16.bf16.f32 " \
                 "{%0,%1,%2,%3}, {%4,%5,%6,%7}, {%8,%9}, {%0,%1,%2,%3};" \
                 : "+f"((d)[0]), "+f"((d)[1]), "+f"((d)[2]), "+f"((d)[3]) \
                 : "r"((a)[0]), "r"((a)[1]), "r"((a)[2]), "r"((a)[3]), \
                   "r"((b)[0]), "r"((b)[1]))

__device__ __forceinline__ void atomicMaxFloat(float* addr, float value) {
    if (value >= 0.0f) atomicMax(reinterpret_cast<int*>(addr), __float_as_int(value));
    else               atomicMin(reinterpret_cast<unsigned int*>(addr), __float_as_uint(value));
}

// split 8 fp32 -> 8 bf16 hi + 8 bf16 lo (packed uint4 each)
__device__ __forceinline__ void cvt8(const float4 f0, const float4 f1, uint4& h, uint4& l) {
    float ff[8] = {f0.x, f0.y, f0.z, f0.w, f1.x, f1.y, f1.z, f1.w};
    unsigned hs[8], ls[8];
#pragma unroll
    for (int i = 0; i < 8; i++) {
        __nv_bfloat16 hb = __float2bfloat16(ff[i]);
        __nv_bfloat16 lb = __float2bfloat16(ff[i] - __bfloat162float(hb));
        hs[i] = *(unsigned short*)&hb;
        ls[i] = *(unsigned short*)&lb;
    }
    h = make_uint4(hs[0] | (hs[1] << 16), hs[2] | (hs[3] << 16),
                   hs[4] | (hs[5] << 16), hs[6] | (hs[7] << 16));
    l = make_uint4(ls[0] | (ls[1] << 16), ls[2] | (ls[3] << 16),
                   ls[4] | (ls[5] << 16), ls[6] | (ls[7] << 16));
}

// ---------------- mma pieces ----------------
__device__ __forceinline__ void load_B(uint32_t sB, const char* bbase, int tid) {
#pragma unroll
    for (int i = 0; i < 4; i++) {
        int idx = i * 256 + tid;
        int row = idx >> 3, col = (idx & 7) << 4;
        CP_ASYNC16(sB + SWZ(row * 128 + col), bbase + (size_t)row * 768 + col);
    }
}

__device__ __forceinline__ void compute_stage(uint32_t sA, uint32_t sB,
                                              float acc[2][8][4],
                                              int lane, int warp_m, int warp_n) {
    const int g = lane >> 3, lr = lane & 7;
#pragma unroll
    for (int ks = 0; ks < 4; ks++) {
        uint32_t a[2][4];
#pragma unroll
        for (int mi = 0; mi < 2; mi++) {
            int row = warp_m * 32 + mi * 16 + lr + ((g & 1) << 3);
            int kb  = ks * 32 + ((g >> 1) << 4);
            LDSM_X4(a[mi][0], a[mi][1], a[mi][2], a[mi][3], sA + SWZ(row * 128 + kb));
        }
        uint32_t b[8][2];
#pragma unroll
        for (int nj2 = 0; nj2 < 4; nj2++) {
            int nrow = warp_n * 64 + nj2 * 16 + lr + ((g >> 1) << 3);
            int kb   = ks * 32 + ((g & 1) << 4);
            uint32_t r0, r1, r2, r3;
            LDSM_X4(r0, r1, r2, r3, sB + SWZ(nrow * 128 + kb));
            b[nj2 * 2][0] = r0;     b[nj2 * 2][1] = r1;
            b[nj2 * 2 + 1][0] = r2; b[nj2 * 2 + 1][1] = r3;
        }
#pragma unroll
        for (int mi = 0; mi < 2; mi++)
#pragma unroll
            for (int nj = 0; nj < 8; nj++)
                MMA16816(acc[mi][nj], a[mi], b[nj]);
    }
}

// A resident (4x16KB tiles: hi k0, hi k1, lo k0, lo k1), B 3-stage pipelined.
// smem: [0,64K) A tiles, [64K,112K) B stages. Caller must have s_ord synced.
__device__ __forceinline__ void mma_resident(const float* __restrict__ x,
                                             const __nv_bfloat16* __restrict__ Bmat,
                                             int bcol0, char* smem, uint32_t sbase,
                                             float acc[2][8][4], int tid, int lane,
                                             int warp_m, int warp_n, const int* s_ord) {
    const uint32_t sB[3] = {sbase + 65536, sbase + 81920, sbase + 98304};
    const char* bb = (const char*)Bmat + (size_t)bcol0 * (KTOT * 2);

    // B prologue: stages 0,1
    load_B(sB[0], bb, tid);           CP_COMMIT();
    load_B(sB[1], bb + 128, tid);     CP_COMMIT();

    // A convert: gathered fp32 rows -> hi/lo bf16 tiles (SW128)
#pragma unroll
    for (int kt = 0; kt < 2; kt++)
#pragma unroll
        for (int i = 0; i < 4; i++) {
            int idx = i * 256 + tid;
            int row = idx >> 3, colb = (idx & 7) << 4;   // byte col in 128B tile
            const float* src = x + (size_t)s_ord[row] * C_IN + kt * 64 + (colb >> 1);
            float4 f0 = __ldg(reinterpret_cast<const float4*>(src));
            float4 f1 = __ldg(reinterpret_cast<const float4*>(src) + 1);
            uint4 h, l;
            cvt8(f0, f1, h, l);
            *reinterpret_cast<uint4*>(smem + kt * 16384 + SWZ(row * 128 + colb)) = h;
            *reinterpret_cast<uint4*>(smem + 32768 + kt * 16384 + SWZ(row * 128 + colb)) = l;
        }
    __syncthreads();

    const uint32_t sA[NCHUNK] = {sbase, sbase + 16384, sbase + 32768, sbase + 49152,
                                 sbase, sbase + 16384};
#pragma unroll
    for (int c = 0; c < NCHUNK; c++) {
        if (c < NCHUNK - 1) CP_WAIT1(); else CP_WAIT0();
        __syncthreads();
        if (c + 2 < NCHUNK) { load_B(sB[(c + 2) % 3], bb + (c + 2) * 128, tid); CP_COMMIT(); }
        compute_stage(sA[c], sB[c % 3], acc, lane, warp_m, warp_n);
    }
    __syncthreads();   // epilogue may reuse A smem region
}

// ---------------- counting sort ----------------
__global__ void k_zero_count() {
    int i = blockIdx.x * 256 + threadIdx.x;
    if (i < V_PAD) g_count[i] = 0;
}

__global__ void k_hist(const int* __restrict__ vid) {
    int e = blockIdx.x * 256 + threadIdx.x;
    atomicAdd(&g_count[__ldg(&vid[e])], 1u);
}

__global__ void k_scan_part() {   // 196 blocks x 256
    __shared__ unsigned s[256];
    int b = blockIdx.x, t = threadIdx.x, i = b * 256 + t;
    s[t] = (i < V_PAD) ? g_count[i] : 0u;
    __syncthreads();
    for (int o = 128; o > 0; o >>= 1) {
        if (t < o) s[t] += s[t + o];
        __syncthreads();
    }
    if (t == 0) g_bsum[b] = s[0];
}

__global__ void k_scan_top() {    // 1 block x 256: exclusive scan of block sums
    __shared__ unsigned s[256];
    int t = threadIdx.x;
    unsigned v = (t < 196) ? g_bsum[t] : 0u;
    s[t] = v;
    __syncthreads();
    for (int o = 1; o < 256; o <<= 1) {
        unsigned u = (t >= o) ? s[t - o] : 0u;
        __syncthreads();
        s[t] += u;
        __syncthreads();
    }
    g_btop[t] = s[t] - v;
}

__global__ void k_scan_out() {    // 196 blocks x 256
    __shared__ unsigned s[256];
    int b = blockIdx.x, t = threadIdx.x, i = b * 256 + t;
    unsigned c = (i < V_PAD) ? g_count[i] : 0u;
    s[t] = c;
    __syncthreads();
    for (int o = 1; o < 256; o <<= 1) {
        unsigned u = (t >= o) ? s[t - o] : 0u;
        __syncthreads();
        s[t] += u;
        __syncthreads();
    }
    if (i < V_PAD) g_offset[i] = g_btop[b] + s[t] - c;
}

__global__ void k_scatter(const int* __restrict__ vid) {
    int e = blockIdx.x * 256 + threadIdx.x;
    int v = __ldg(&vid[e]);
    unsigned p = atomicAdd(&g_offset[v], 1u);
    g_order[p] = e;
    g_svid[p] = v;
}

// ---------------- prep ----------------
__global__ void k_prep_w(const float* __restrict__ W1,
                         const float* __restrict__ W2e,
                         const float* __restrict__ W2v) {
    int i = blockIdx.x * 256 + threadIdx.x;
    if (i < C_MID * C_IN) {
        int n = i >> 7, k = i & 127;
        float w = W1[i];
        __nv_bfloat16 hi = __float2bfloat16(w);
        __nv_bfloat16 lo = __float2bfloat16(w - __bfloat162float(hi));
        g_B1[n * KTOT + k] = hi;
        g_B1[n * KTOT + 128 + k] = hi;
        g_B1[n * KTOT + 256 + k] = lo;
    }
    if (i < C_OUT * C_IN) {
        int n = i >> 7, k = i & 127;
        float w = W2e[i];
        __nv_bfloat16 hi = __float2bfloat16(w);
        __nv_bfloat16 lo = __float2bfloat16(w - __bfloat162float(hi));
        g_B3[n * KTOT + k] = hi;
        g_B3[n * KTOT + 128 + k] = hi;
        g_B3[n * KTOT + 256 + k] = lo;
    }
    if (i < C_MID * C_OUT) {
        int k = i >> 7, n = i & 127;
        g_Wt2v[i] = W2v[n * C_MID + k];
    }
}

__global__ void k_init_zvmax() {
    int i = blockIdx.x * blockDim.x + threadIdx.x;
    const float NEG_INF = __int_as_float(0xFF800000);
    if (i < (V_PAD * C_MID) / 4)
        reinterpret_cast<float4*>(g_zvmax)[i] = make_float4(NEG_INF, NEG_INF, NEG_INF, NEG_INF);
}

// ---------------- GEMM1: z = xs@W1^T, in-tile run-max, few atomics ----------------
__global__ void __launch_bounds__(256, 2)
k_mma1(const float* __restrict__ x) {
    extern __shared__ char smem[];
    uint32_t sbase = smem_to_u32(smem);
    __shared__ int s_ord[128];
    __shared__ int s_vid[128];
    const int tid = threadIdx.x, wid = tid >> 5, lane = tid & 31;
    const int warp_m = wid & 3, warp_n = wid >> 2;
    const int arow0 = blockIdx.y * 128, bcol0 = blockIdx.x * 128;

    if (tid < 128) s_ord[tid] = __ldg(&g_order[arow0 + tid]);
    __syncthreads();

    float acc[2][8][4] = {};
    mma_resident(x, g_B1, bcol0, smem, sbase, acc, tid, lane, warp_m, warp_n, s_ord);

    // dump fragments to smem [128 rows][stride 132]
    float* s_acc = reinterpret_cast<float*>(smem);
    const int lr4 = lane >> 2, lc2 = (lane & 3) * 2;
#pragma unroll
    for (int mi = 0; mi < 2; mi++) {
        int r0 = warp_m * 32 + mi * 16 + lr4;
#pragma unroll
        for (int nj = 0; nj < 8; nj++) {
            int col = warp_n * 64 + nj * 8 + lc2;
            s_acc[r0 * 132 + col]           = acc[mi][nj][0];
            s_acc[r0 * 132 + col + 1]       = acc[mi][nj][1];
            s_acc[(r0 + 8) * 132 + col]     = acc[mi][nj][2];
            s_acc[(r0 + 8) * 132 + col + 1] = acc[mi][nj][3];
        }
    }
    if (tid < 128) s_vid[tid] = __ldg(&g_svid[arow0 + tid]);
    __syncthreads();

    // per-column run-max over sorted rows: ~1 atomic per (vertex run, col)
    const int col = tid & 127;
    const int rbeg = (tid >> 7) * 64;
    int vcur = s_vid[rbeg];
    float cur = s_acc[rbeg * 132 + col];
    for (int r = rbeg + 1; r < rbeg + 64; r++) {
        int v = s_vid[r];
        float val = s_acc[r * 132 + col];
        if (v != vcur) {
            atomicMaxFloat(&g_zvmax[(size_t)vcur * C_MID + bcol0 + col], cur);
            vcur = v;
            cur = val;
        } else {
            cur = fmaxf(cur, val);
        }
    }
    atomicMaxFloat(&g_zvmax[(size_t)vcur * C_MID + bcol0 + col], cur);
}

// ---------------- GEMM3: out[order[p]] = xs@W2e^T + z_vertex[svid[p]] ----------------
__global__ void __launch_bounds__(256, 2)
k_mma3(const float* __restrict__ x, float* __restrict__ out) {
    extern __shared__ char smem[];
    uint32_t sbase = smem_to_u32(smem);
    __shared__ int s_ord[128];
    const int tid = threadIdx.x, wid = tid >> 5, lane = tid & 31;
    const int warp_m = wid & 3, warp_n = wid >> 2;
    const int arow0 = blockIdx.y * 128;

    if (tid < 128) s_ord[tid] = __ldg(&g_order[arow0 + tid]);
    __syncthreads();

    float acc[2][8][4] = {};
    mma_resident(x, g_B3, 0, smem, sbase, acc, tid, lane, warp_m, warp_n, s_ord);

    const int lr4 = lane >> 2, lc2 = (lane & 3) * 2;
#pragma unroll
    for (int mi = 0; mi < 2; mi++) {
        int p0 = warp_m * 32 + mi * 16 + lr4;
        int p1 = p0 + 8;
        int v0 = __ldg(&g_svid[arow0 + p0]);
        int v1 = __ldg(&g_svid[arow0 + p1]);
        int e0 = s_ord[p0];
        int e1 = s_ord[p1];
        const float* z0 = g_zvertex + (size_t)v0 * C_OUT + warp_n * 64 + lc2;
        const float* z1 = g_zvertex + (size_t)v1 * C_OUT + warp_n * 64 + lc2;
        float* o0 = out + (size_t)e0 * C_OUT + warp_n * 64 + lc2;
        float* o1 = out + (size_t)e1 * C_OUT + warp_n * 64 + lc2;
#pragma unroll
        for (int nj = 0; nj < 8; nj++) {
            float2 za = __ldg(reinterpret_cast<const float2*>(z0 + nj * 8));
            float2 zb = __ldg(reinterpret_cast<const float2*>(z1 + nj * 8));
            *reinterpret_cast<float2*>(o0 + nj * 8) =
                make_float2(acc[mi][nj][0] + za.x, acc[mi][nj][1] + za.y);
            *reinterpret_cast<float2*>(o1 + nj * 8) =
                make_float2(acc[mi][nj][2] + zb.x, acc[mi][nj][3] + zb.y);
        }
    }
}

// ---------------- GEMM2 (FFMA, small): z_vertex = fix(z_vmax + b1) @ W2v^T ----------------
#define FMA_F32X2(d, a, b) asm("fma.rn.f32x2 %0, %1, %2, %0;" : "+l"(d) : "l"(a), "l"(b))
#define DUP_F32X2(d, s)    asm("mov.b64 %0, {%1, %1};" : "=l"(d) : "f"(s))
__device__ __forceinline__ float lo32(unsigned long long v) {
    return __uint_as_float((unsigned)(v & 0xffffffffull));
}
__device__ __forceinline__ float hi32(unsigned long long v) {
    return __uint_as_float((unsigned)(v >> 32));
}

__global__ void __launch_bounds__(256, 2)
k_gemm2(const float* __restrict__ b1) {
    __shared__ float As[16][132];
    __shared__ float Bs[16][128];
    unsigned long long acc[8][4] = {};
    const int arow0 = blockIdx.x * 128;
    const int tid = threadIdx.x;
    const int tr = (tid >> 4) << 3, tc = (tid & 15) << 3;
    const int lrow = tid >> 1, lf4 = (tid & 1) << 1;
    const int brow = tid >> 4, bc4 = tid & 15;

    for (int k0 = 0; k0 < C_MID; k0 += 16) {
        const float4* asrc = reinterpret_cast<const float4*>(
            g_zvmax + (size_t)(arow0 + lrow) * C_MID + k0);
        float4 v0 = __ldg(asrc + lf4);
        float4 v1 = __ldg(asrc + lf4 + 1);
        float4 bb0 = *reinterpret_cast<const float4*>(&b1[k0 + lf4 * 4]);
        float4 bb1 = *reinterpret_cast<const float4*>(&b1[k0 + lf4 * 4 + 4]);
        v0.x = (v0.x < -1e38f) ? 0.0f : v0.x + bb0.x;
        v0.y = (v0.y < -1e38f) ? 0.0f : v0.y + bb0.y;
        v0.z = (v0.z < -1e38f) ? 0.0f : v0.z + bb0.z;
        v0.w = (v0.w < -1e38f) ? 0.0f : v0.w + bb0.w;
        v1.x = (v1.x < -1e38f) ? 0.0f : v1.x + bb1.x;
        v1.y = (v1.y < -1e38f) ? 0.0f : v1.y + bb1.y;
        v1.z = (v1.z < -1e38f) ? 0.0f : v1.z + bb1.z;
        v1.w = (v1.w < -1e38f) ? 0.0f : v1.w + bb1.w;
        {
            int kk = lf4 << 2;
            As[kk + 0][lrow] = v0.x;  As[kk + 1][lrow] = v0.y;
            As[kk + 2][lrow] = v0.z;  As[kk + 3][lrow] = v0.w;
            As[kk + 4][lrow] = v1.x;  As[kk + 5][lrow] = v1.y;
            As[kk + 6][lrow] = v1.z;  As[kk + 7][lrow] = v1.w;
        }
        const float4* bsrc = reinterpret_cast<const float4*>(
            g_Wt2v + (size_t)(k0 + brow) * C_OUT);
        float4 w0 = __ldg(bsrc + bc4);
        float4 w1 = __ldg(bsrc + bc4 + 16);
        *reinterpret_cast<float4*>(&Bs[brow][(bc4 << 2)])      = w0;
        *reinterpret_cast<float4*>(&Bs[brow][(bc4 << 2) + 64]) = w1;
        __syncthreads();
#pragma unroll
        for (int k = 0; k < 16; k++) {
            float4 aq0 = *reinterpret_cast<const float4*>(&As[k][tr]);
            float4 aq1 = *reinterpret_cast<const float4*>(&As[k][tr + 4]);
            ulonglong2 b0 = *reinterpret_cast<const ulonglong2*>(&Bs[k][tc]);
            ulonglong2 b1v = *reinterpret_cast<const ulonglong2*>(&Bs[k][tc + 4]);
            unsigned long long b2[4] = {b0.x, b0.y, b1v.x, b1v.y};
            float af[8] = {aq0.x, aq0.y, aq0.z, aq0.w, aq1.x, aq1.y, aq1.z, aq1.w};
            unsigned long long a2[8];
#pragma unroll
            for (int i = 0; i < 8; i++) DUP_F32X2(a2[i], af[i]);
#pragma unroll
            for (int i = 0; i < 8; i++)
#pragma unroll
                for (int j = 0; j < 4; j++) FMA_F32X2(acc[i][j], a2[i], b2[j]);
        }
        __syncthreads();
    }
#pragma unroll
    for (int i = 0; i < 8; i++) {
        int vrow = arow0 + tr + i;
        if (vrow < V_SEG) {
            float4 o0 = make_float4(lo32(acc[i][0]), hi32(acc[i][0]),
                                    lo32(acc[i][1]), hi32(acc[i][1]));
            float4 o1 = make_float4(lo32(acc[i][2]), hi32(acc[i][2]),
                                    lo32(acc[i][3]), hi32(acc[i][3]));
            *reinterpret_cast<float4*>(&g_zvertex[(size_t)vrow * C_OUT + tc])     = o0;
            *reinterpret_cast<float4*>(&g_zvertex[(size_t)vrow * C_OUT + tc + 4]) = o1;
        }
    }
}

// ---------------- launch ----------------
static constexpr int SMEM_MMA = 65536 + 3 * 16384;   // 112 KB: A 64KB + B 3x16KB

extern "C" void kernel_launch(void* const* d_in, const int* in_sizes, int n_in,
                              void* d_out, int out_size) {
    const float* x   = (const float*)d_in[0];
    const int*   vid = (const int*)d_in[1];
    const float* W1  = (const float*)d_in[2];
    const float* b1  = (const float*)d_in[3];
    const float* W2e = (const float*)d_in[4];
    const float* W2v = (const float*)d_in[5];
    float* out = (float*)d_out;

    cudaFuncSetAttribute(k_mma1, cudaFuncAttributeMaxDynamicSharedMemorySize, SMEM_MMA);
    cudaFuncSetAttribute(k_mma3, cudaFuncAttributeMaxDynamicSharedMemorySize, SMEM_MMA);

    k_prep_w<<<128, 256>>>(W1, W2e, W2v);
    k_zero_count<<<(V_PAD + 255) / 256, 256>>>();
    k_hist<<<E_EDGES / 256, 256>>>(vid);
    k_scan_part<<<196, 256>>>();
    k_scan_top<<<1, 256>>>();
    k_scan_out<<<196, 256>>>();
    k_scatter<<<E_EDGES / 256, 256>>>(vid);
    k_init_zvmax<<<(V_PAD * C_MID / 4 + 255) / 256, 256>>>();
    k_mma1<<<dim3(2, E_EDGES / 128), 256, SMEM_MMA>>>(x);
    k_gemm2<<<V_PAD / 128, 256>>>(b1);
    k_mma3<<<dim3(1, E_EDGES / 128), 256, SMEM_MMA>>>(x, out);
}

// round 7
// speedup vs baseline: 1.1299x; 1.1299x over previous
#include <cuda_runtime.h>
#include <cuda_bf16.h>
#include <cstdint>

#define E_EDGES   1048576
#define V_SEG     50000
#define V_PAD     50048
#define C_IN      128
#define C_MID     256
#define C_OUT     128
#define KTOT      384      // 3 x 128 split-K (hi*whi + lo*whi + hi*wlo)
#define NCHUNK    6        // KTOT / 64

// ---------------- device scratch ----------------
__device__ __align__(16) __nv_bfloat16 g_xhi[(size_t)E_EDGES * C_IN];   // sorted order
__device__ __align__(16) __nv_bfloat16 g_xlo[(size_t)E_EDGES * C_IN];   // sorted order
__device__ __align__(16) __nv_bfloat16 g_B1[C_MID * KTOT];   // [256][384] = [Whi|Whi|Wlo]
__device__ __align__(16) __nv_bfloat16 g_B3[C_OUT * KTOT];   // [128][384]
__device__ float g_Wt2v[C_MID * C_OUT];                      // W2v^T (256 x 128)
__device__ float g_zvmax[V_PAD * C_MID];
__device__ float g_zvertex[V_SEG * C_OUT];
// counting sort
__device__ unsigned g_count[V_PAD];
__device__ unsigned g_offset[V_PAD];
__device__ unsigned g_bsum[256];
__device__ unsigned g_btop[256];
__device__ int g_order[E_EDGES];   // sorted pos -> original edge
__device__ int g_svid[E_EDGES];    // vid in sorted order (non-decreasing)

// ---------------- helpers ----------------
__device__ __forceinline__ uint32_t smem_to_u32(const void* p) {
    uint32_t a;
    asm("{ .reg .u64 t; cvta.to.shared.u64 t, %1; cvt.u32.u64 %0, t; }" : "=r"(a) : "l"(p));
    return a;
}
#define SWZ(o) ((o) ^ (((o) >> 3) & 0x70))

#define CP_ASYNC16(dst, src) \
    asm volatile("cp.async.cg.shared.global [%0], [%1], 16;" :: "r"(dst), "l"(src))
#define CP_COMMIT() asm volatile("cp.async.commit_group;" ::: "memory")
#define CP_WAIT1()  asm volatile("cp.async.wait_group 1;" ::: "memory")
#define CP_WAIT0()  asm volatile("cp.async.wait_group 0;" ::: "memory")

#define LDSM_X4(r0, r1, r2, r3, addr) \
    asm volatile("ldmatrix.sync.aligned.m8n8.x4.shared.b16 {%0,%1,%2,%3}, [%4];" \
                 : "=r"(r0), "=r"(r1), "=r"(r2), "=r"(r3) : "r"(addr))

#define MMA16816(d, a, b) \
    asm volatile("mma.sync.aligned.m16n8k16.row.col.f32.bf16.bf16.f32 " \
                 "{%0,%1,%2,%3}, {%4,%5,%6,%7}, {%8,%9}, {%0,%1,%2,%3};" \
                 : "+f"((d)[0]), "+f"((d)[1]), "+f"((d)[2]), "+f"((d)[3]) \
                 : "r"((a)[0]), "r"((a)[1]), "r"((a)[2]), "r"((a)[3]), \
                   "r"((b)[0]), "r"((b)[1]))

__device__ __forceinline__ void atomicMaxFloat(float* addr, float value) {
    if (value >= 0.0f) atomicMax(reinterpret_cast<int*>(addr), __float_as_int(value));
    else               atomicMin(reinterpret_cast<unsigned int*>(addr), __float_as_uint(value));
}

// ---------------- mma pieces ----------------
__device__ __forceinline__ void load_B(uint32_t sB, const char* bbase, int tid) {
#pragma unroll
    for (int i = 0; i < 4; i++) {
        int idx = i * 256 + tid;
        int row = idx >> 3, col = (idx & 7) << 4;
        CP_ASYNC16(sB + SWZ(row * 128 + col), bbase + (size_t)row * 768 + col);
    }
}

__device__ __forceinline__ void compute_stage(uint32_t sA, uint32_t sB,
                                              float acc[2][8][4],
                                              int lane, int warp_m, int warp_n) {
    const int g = lane >> 3, lr = lane & 7;
#pragma unroll
    for (int ks = 0; ks < 4; ks++) {
        uint32_t a[2][4];
#pragma unroll
        for (int mi = 0; mi < 2; mi++) {
            int row = warp_m * 32 + mi * 16 + lr + ((g & 1) << 3);
            int kb  = ks * 32 + ((g >> 1) << 4);
            LDSM_X4(a[mi][0], a[mi][1], a[mi][2], a[mi][3], sA + SWZ(row * 128 + kb));
        }
        uint32_t b[8][2];
#pragma unroll
        for (int nj2 = 0; nj2 < 4; nj2++) {
            int nrow = warp_n * 64 + nj2 * 16 + lr + ((g >> 1) << 3);
            int kb   = ks * 32 + ((g & 1) << 4);
            uint32_t r0, r1, r2, r3;
            LDSM_X4(r0, r1, r2, r3, sB + SWZ(nrow * 128 + kb));
            b[nj2 * 2][0] = r0;     b[nj2 * 2][1] = r1;
            b[nj2 * 2 + 1][0] = r2; b[nj2 * 2 + 1][1] = r3;
        }
#pragma unroll
        for (int mi = 0; mi < 2; mi++)
#pragma unroll
            for (int nj = 0; nj < 8; nj++)
                MMA16816(acc[mi][nj], a[mi], b[nj]);
    }
}

// A resident in smem (4x16KB: hi k0, hi k1, lo k0, lo k1) loaded ONCE from the
// presplit sorted arrays; B double-buffered (2x16KB). smem total 96 KB.
__device__ __forceinline__ void mma_mainloop(const __nv_bfloat16* __restrict__ Bmat,
                                             int arow0, int bcol0,
                                             uint32_t sbase, float acc[2][8][4],
                                             int tid, int lane, int warp_m, int warp_n) {
    const uint32_t sB[2] = {sbase + 65536, sbase + 81920};
    const char* xh = (const char*)g_xhi + (size_t)arow0 * 256;
    const char* xl = (const char*)g_xlo + (size_t)arow0 * 256;
    const char* bb = (const char*)Bmat + (size_t)bcol0 * (KTOT * 2);

    // A: one cp.async group, 64 KB, coalesced (row stride 256 B, tile k-offset 128 B)
    const char* asrc[4] = {xh, xh + 128, xl, xl + 128};
#pragma unroll
    for (int t = 0; t < 4; t++)
#pragma unroll
        for (int i = 0; i < 4; i++) {
            int idx = i * 256 + tid;
            int row = idx >> 3, col = (idx & 7) << 4;
            CP_ASYNC16(sbase + t * 16384 + SWZ(row * 128 + col),
                       asrc[t] + (size_t)row * 256 + col);
        }
    CP_COMMIT();
    load_B(sB[0], bb, tid);
    CP_COMMIT();

    const uint32_t sAoff[NCHUNK] = {0, 16384, 32768, 49152, 0, 16384};
#pragma unroll
    for (int c = 0; c < NCHUNK; c++) {
        if (c < NCHUNK - 1) {
            load_B(sB[(c + 1) & 1], bb + (c + 1) * 128, tid);
            CP_COMMIT();
            CP_WAIT1();
        } else {
            CP_WAIT0();
        }
        __syncthreads();
        compute_stage(sbase + sAoff[c], sB[c & 1], acc, lane, warp_m, warp_n);
        __syncthreads();
    }
}

// ---------------- counting sort ----------------
__global__ void k_zero_count() {
    int i = blockIdx.x * 256 + threadIdx.x;
    if (i < V_PAD) g_count[i] = 0;
}

__global__ void k_hist(const int* __restrict__ vid) {
    int e = blockIdx.x * 256 + threadIdx.x;
    atomicAdd(&g_count[__ldg(&vid[e])], 1u);
}

__global__ void k_scan_part() {   // 196 blocks x 256
    __shared__ unsigned s[256];
    int b = blockIdx.x, t = threadIdx.x, i = b * 256 + t;
    s[t] = (i < V_PAD) ? g_count[i] : 0u;
    __syncthreads();
    for (int o = 128; o > 0; o >>= 1) {
        if (t < o) s[t] += s[t + o];
        __syncthreads();
    }
    if (t == 0) g_bsum[b] = s[0];
}

__global__ void k_scan_top() {    // 1 block x 256: exclusive scan of block sums
    __shared__ unsigned s[256];
    int t = threadIdx.x;
    unsigned v = (t < 196) ? g_bsum[t] : 0u;
    s[t] = v;
    __syncthreads();
    for (int o = 1; o < 256; o <<= 1) {
        unsigned u = (t >= o) ? s[t - o] : 0u;
        __syncthreads();
        s[t] += u;
        __syncthreads();
    }
    g_btop[t] = s[t] - v;
}

__global__ void k_scan_out() {    // 196 blocks x 256
    __shared__ unsigned s[256];
    int b = blockIdx.x, t = threadIdx.x, i = b * 256 + t;
    unsigned c = (i < V_PAD) ? g_count[i] : 0u;
    s[t] = c;
    __syncthreads();
    for (int o = 1; o < 256; o <<= 1) {
        unsigned u = (t >= o) ? s[t - o] : 0u;
        __syncthreads();
        s[t] += u;
        __syncthreads();
    }
    if (i < V_PAD) g_offset[i] = g_btop[b] + s[t] - c;
}

__global__ void k_scatter(const int* __restrict__ vid) {
    int e = blockIdx.x * 256 + threadIdx.x;
    int v = __ldg(&vid[e]);
    unsigned p = atomicAdd(&g_offset[v], 1u);
    g_order[p] = e;
    g_svid[p] = v;
}

// ---------------- prep ----------------
__global__ void k_prep_w(const float* __restrict__ W1,
                         const float* __restrict__ W2e,
                         const float* __restrict__ W2v) {
    int i = blockIdx.x * 256 + threadIdx.x;
    if (i < C_MID * C_IN) {
        int n = i >> 7, k = i & 127;
        float w = W1[i];
        __nv_bfloat16 hi = __float2bfloat16(w);
        __nv_bfloat16 lo = __float2bfloat16(w - __bfloat162float(hi));
        g_B1[n * KTOT + k] = hi;
        g_B1[n * KTOT + 128 + k] = hi;
        g_B1[n * KTOT + 256 + k] = lo;
    }
    if (i < C_OUT * C_IN) {
        int n = i >> 7, k = i & 127;
        float w = W2e[i];
        __nv_bfloat16 hi = __float2bfloat16(w);
        __nv_bfloat16 lo = __float2bfloat16(w - __bfloat162float(hi));
        g_B3[n * KTOT + k] = hi;
        g_B3[n * KTOT + 128 + k] = hi;
        g_B3[n * KTOT + 256 + k] = lo;
    }
    if (i < C_MID * C_OUT) {
        int k = i >> 7, n = i & 127;
        g_Wt2v[i] = W2v[n * C_MID + k];
    }
}

// gather-split: sorted row p <- original edge order[p]
__global__ void k_split_x(const float* __restrict__ x) {
    size_t i = (size_t)blockIdx.x * 256 + threadIdx.x;   // unit = 4 floats
    int prow = (int)(i >> 5);            // 32 units per 128-float row
    int q = (int)(i & 31);
    int e = __ldg(&g_order[prow]);
    float4 v = __ldg(reinterpret_cast<const float4*>(x + (size_t)e * C_IN) + q);
    ushort4 h, l;
    __nv_bfloat16 hb, lb;
    hb = __float2bfloat16(v.x); lb = __float2bfloat16(v.x - __bfloat162float(hb));
    h.x = *(unsigned short*)&hb; l.x = *(unsigned short*)&lb;
    hb = __float2bfloat16(v.y); lb = __float2bfloat16(v.y - __bfloat162float(hb));
    h.y = *(unsigned short*)&hb; l.y = *(unsigned short*)&lb;
    hb = __float2bfloat16(v.z); lb = __float2bfloat16(v.z - __bfloat162float(hb));
    h.z = *(unsigned short*)&hb; l.z = *(unsigned short*)&lb;
    hb = __float2bfloat16(v.w); lb = __float2bfloat16(v.w - __bfloat162float(hb));
    h.w = *(unsigned short*)&hb; l.w = *(unsigned short*)&lb;
    reinterpret_cast<ushort4*>(g_xhi)[i] = h;
    reinterpret_cast<ushort4*>(g_xlo)[i] = l;
}

__global__ void k_init_zvmax() {
    int i = blockIdx.x * blockDim.x + threadIdx.x;
    const float NEG_INF = __int_as_float(0xFF800000);
    if (i < (V_PAD * C_MID) / 4)
        reinterpret_cast<float4*>(g_zvmax)[i] = make_float4(NEG_INF, NEG_INF, NEG_INF, NEG_INF);
}

// ---------------- GEMM1: z = xs@W1^T, in-tile run-max, few atomics ----------------
__global__ void __launch_bounds__(256, 2)
k_mma1() {
    extern __shared__ char smem[];
    uint32_t sbase = smem_to_u32(smem);
    __shared__ int s_vid[128];
    const int tid = threadIdx.x, wid = tid >> 5, lane = tid & 31;
    const int warp_m = wid & 3, warp_n = wid >> 2;
    const int arow0 = blockIdx.y * 128, bcol0 = blockIdx.x * 128;

    float acc[2][8][4] = {};
    mma_mainloop(g_B1, arow0, bcol0, sbase, acc, tid, lane, warp_m, warp_n);

    // dump fragments to smem [128 rows][stride 132]
    float* s_acc = reinterpret_cast<float*>(smem);
    const int lr4 = lane >> 2, lc2 = (lane & 3) * 2;
#pragma unroll
    for (int mi = 0; mi < 2; mi++) {
        int r0 = warp_m * 32 + mi * 16 + lr4;
#pragma unroll
        for (int nj = 0; nj < 8; nj++) {
            int col = warp_n * 64 + nj * 8 + lc2;
            s_acc[r0 * 132 + col]           = acc[mi][nj][0];
            s_acc[r0 * 132 + col + 1]       = acc[mi][nj][1];
            s_acc[(r0 + 8) * 132 + col]     = acc[mi][nj][2];
            s_acc[(r0 + 8) * 132 + col + 1] = acc[mi][nj][3];
        }
    }
    if (tid < 128) s_vid[tid] = __ldg(&g_svid[arow0 + tid]);
    __syncthreads();

    // per-column run-max over sorted rows: ~1 atomic per (vertex run, col)
    const int col = tid & 127;
    const int rbeg = (tid >> 7) * 64;
    int vcur = s_vid[rbeg];
    float cur = s_acc[rbeg * 132 + col];
    for (int r = rbeg + 1; r < rbeg + 64; r++) {
        int v = s_vid[r];
        float val = s_acc[r * 132 + col];
        if (v != vcur) {
            atomicMaxFloat(&g_zvmax[(size_t)vcur * C_MID + bcol0 + col], cur);
            vcur = v;
            cur = val;
        } else {
            cur = fmaxf(cur, val);
        }
    }
    atomicMaxFloat(&g_zvmax[(size_t)vcur * C_MID + bcol0 + col], cur);
}

// ---------------- GEMM3: out[order[p]] = xs@W2e^T + z_vertex[svid[p]] ----------------
__global__ void __launch_bounds__(256, 2)
k_mma3(float* __restrict__ out) {
    extern __shared__ char smem[];
    uint32_t sbase = smem_to_u32(smem);
    const int tid = threadIdx.x, wid = tid >> 5, lane = tid & 31;
    const int warp_m = wid & 3, warp_n = wid >> 2;
    const int arow0 = blockIdx.y * 128;

    float acc[2][8][4] = {};
    mma_mainloop(g_B3, arow0, 0, sbase, acc, tid, lane, warp_m, warp_n);

    const int lr4 = lane >> 2, lc2 = (lane & 3) * 2;
#pragma unroll
    for (int mi = 0; mi < 2; mi++) {
        int p0 = arow0 + warp_m * 32 + mi * 16 + lr4;
        int p1 = p0 + 8;
        int v0 = __ldg(&g_svid[p0]);
        int v1 = __ldg(&g_svid[p1]);
        int e0 = __ldg(&g_order[p0]);
        int e1 = __ldg(&g_order[p1]);
        const float* z0 = g_zvertex + (size_t)v0 * C_OUT + warp_n * 64 + lc2;
        const float* z1 = g_zvertex + (size_t)v1 * C_OUT + warp_n * 64 + lc2;
        float* o0 = out + (size_t)e0 * C_OUT + warp_n * 64 + lc2;
        float* o1 = out + (size_t)e1 * C_OUT + warp_n * 64 + lc2;
#pragma unroll
        for (int nj = 0; nj < 8; nj++) {
            float2 za = __ldg(reinterpret_cast<const float2*>(z0 + nj * 8));
            float2 zb = __ldg(reinterpret_cast<const float2*>(z1 + nj * 8));
            *reinterpret_cast<float2*>(o0 + nj * 8) =
                make_float2(acc[mi][nj][0] + za.x, acc[mi][nj][1] + za.y);
            *reinterpret_cast<float2*>(o1 + nj * 8) =
                make_float2(acc[mi][nj][2] + zb.x, acc[mi][nj][3] + zb.y);
        }
    }
}

// ---------------- GEMM2 (FFMA, small): z_vertex = fix(z_vmax + b1) @ W2v^T ----------------
#define FMA_F32X2(d, a, b) asm("fma.rn.f32x2 %0, %1, %2, %0;" : "+l"(d) : "l"(a), "l"(b))
#define DUP_F32X2(d, s)    asm("mov.b64 %0, {%1, %1};" : "=l"(d) : "f"(s))
__device__ __forceinline__ float lo32(unsigned long long v) {
    return __uint_as_float((unsigned)(v & 0xffffffffull));
}
__device__ __forceinline__ float hi32(unsigned long long v) {
    return __uint_as_float((unsigned)(v >> 32));
}

__global__ void __launch_bounds__(256, 2)
k_gemm2(const float* __restrict__ b1) {
    __shared__ float As[16][132];
    __shared__ float Bs[16][128];
    unsigned long long acc[8][4] = {};
    const int arow0 = blockIdx.x * 128;
    const int tid = threadIdx.x;
    const int tr = (tid >> 4) << 3, tc = (tid & 15) << 3;
    const int lrow = tid >> 1, lf4 = (tid & 1) << 1;
    const int brow = tid >> 4, bc4 = tid & 15;

    for (int k0 = 0; k0 < C_MID; k0 += 16) {
        const float4* asrc = reinterpret_cast<const float4*>(
            g_zvmax + (size_t)(arow0 + lrow) * C_MID + k0);
        float4 v0 = __ldg(asrc + lf4);
        float4 v1 = __ldg(asrc + lf4 + 1);
        float4 bb0 = *reinterpret_cast<const float4*>(&b1[k0 + lf4 * 4]);
        float4 bb1 = *reinterpret_cast<const float4*>(&b1[k0 + lf4 * 4 + 4]);
        v0.x = (v0.x < -1e38f) ? 0.0f : v0.x + bb0.x;
        v0.y = (v0.y < -1e38f) ? 0.0f : v0.y + bb0.y;
        v0.z = (v0.z < -1e38f) ? 0.0f : v0.z + bb0.z;
        v0.w = (v0.w < -1e38f) ? 0.0f : v0.w + bb0.w;
        v1.x = (v1.x < -1e38f) ? 0.0f : v1.x + bb1.x;
        v1.y = (v1.y < -1e38f) ? 0.0f : v1.y + bb1.y;
        v1.z = (v1.z < -1e38f) ? 0.0f : v1.z + bb1.z;
        v1.w = (v1.w < -1e38f) ? 0.0f : v1.w + bb1.w;
        {
            int kk = lf4 << 2;
            As[kk + 0][lrow] = v0.x;  As[kk + 1][lrow] = v0.y;
            As[kk + 2][lrow] = v0.z;  As[kk + 3][lrow] = v0.w;
            As[kk + 4][lrow] = v1.x;  As[kk + 5][lrow] = v1.y;
            As[kk + 6][lrow] = v1.z;  As[kk + 7][lrow] = v1.w;
        }
        const float4* bsrc = reinterpret_cast<const float4*>(
            g_Wt2v + (size_t)(k0 + brow) * C_OUT);
        float4 w0 = __ldg(bsrc + bc4);
        float4 w1 = __ldg(bsrc + bc4 + 16);
        *reinterpret_cast<float4*>(&Bs[brow][(bc4 << 2)])      = w0;
        *reinterpret_cast<float4*>(&Bs[brow][(bc4 << 2) + 64]) = w1;
        __syncthreads();
#pragma unroll
        for (int k = 0; k < 16; k++) {
            float4 aq0 = *reinterpret_cast<const float4*>(&As[k][tr]);
            float4 aq1 = *reinterpret_cast<const float4*>(&As[k][tr + 4]);
            ulonglong2 b0 = *reinterpret_cast<const ulonglong2*>(&Bs[k][tc]);
            ulonglong2 b1v = *reinterpret_cast<const ulonglong2*>(&Bs[k][tc + 4]);
            unsigned long long b2[4] = {b0.x, b0.y, b1v.x, b1v.y};
            float af[8] = {aq0.x, aq0.y, aq0.z, aq0.w, aq1.x, aq1.y, aq1.z, aq1.w};
            unsigned long long a2[8];
#pragma unroll
            for (int i = 0; i < 8; i++) DUP_F32X2(a2[i], af[i]);
#pragma unroll
            for (int i = 0; i < 8; i++)
#pragma unroll
                for (int j = 0; j < 4; j++) FMA_F32X2(acc[i][j], a2[i], b2[j]);
        }
        __syncthreads();
    }
#pragma unroll
    for (int i = 0; i < 8; i++) {
        int vrow = arow0 + tr + i;
        if (vrow < V_SEG) {
            float4 o0 = make_float4(lo32(acc[i][0]), hi32(acc[i][0]),
                                    lo32(acc[i][1]), hi32(acc[i][1]));
            float4 o1 = make_float4(lo32(acc[i][2]), hi32(acc[i][2]),
                                    lo32(acc[i][3]), hi32(acc[i][3]));
            *reinterpret_cast<float4*>(&g_zvertex[(size_t)vrow * C_OUT + tc])     = o0;
            *reinterpret_cast<float4*>(&g_zvertex[(size_t)vrow * C_OUT + tc + 4]) = o1;
        }
    }
}

// ---------------- launch ----------------
static constexpr int SMEM_MMA = 65536 + 2 * 16384;   // 96 KB: A 64KB + B 2x16KB

extern "C" void kernel_launch(void* const* d_in, const int* in_sizes, int n_in,
                              void* d_out, int out_size) {
    const float* x   = (const float*)d_in[0];
    const int*   vid = (const int*)d_in[1];
    const float* W1  = (const float*)d_in[2];
    const float* b1  = (const float*)d_in[3];
    const float* W2e = (const float*)d_in[4];
    const float* W2v = (const float*)d_in[5];
    float* out = (float*)d_out;

    cudaFuncSetAttribute(k_mma1, cudaFuncAttributeMaxDynamicSharedMemorySize, SMEM_MMA);
    cudaFuncSetAttribute(k_mma3, cudaFuncAttributeMaxDynamicSharedMemorySize, SMEM_MMA);

    k_prep_w<<<128, 256>>>(W1, W2e, W2v);
    k_zero_count<<<(V_PAD + 255) / 256, 256>>>();
    k_hist<<<E_EDGES / 256, 256>>>(vid);
    k_scan_part<<<196, 256>>>();
    k_scan_top<<<1, 256>>>();
    k_scan_out<<<196, 256>>>();
    k_scatter<<<E_EDGES / 256, 256>>>(vid);
    k_split_x<<<(E_EDGES * C_IN / 4) / 256, 256>>>(x);
    k_init_zvmax<<<(V_PAD * C_MID / 4 + 255) / 256, 256>>>();
    k_mma1<<<dim3(2, E_EDGES / 128), 256, SMEM_MMA>>>();
    k_gemm2<<<V_PAD / 128, 256>>>(b1);
    k_mma3<<<dim3(1, E_EDGES / 128), 256, SMEM_MMA>>>(out);
}

// round 8
// speedup vs baseline: 1.2016x; 1.0634x over previous
#include <cuda_runtime.h>
#include <cuda_bf16.h>
#include <cstdint>

#define E_EDGES   1048576
#define V_SEG     50000
#define V_PAD     50048
#define C_IN      128
#define C_MID     256
#define C_OUT     128
#define KTOT      384      // 3 x 128 split-K (hi*whi + lo*whi + hi*wlo)
#define NCHUNK    6        // KTOT / 64
#define NCHUNK2   12       // gemm2: 3 x 256 / 64

// ---------------- device scratch ----------------
__device__ __align__(16) __nv_bfloat16 g_xhi[(size_t)E_EDGES * C_IN];   // sorted order
__device__ __align__(16) __nv_bfloat16 g_xlo[(size_t)E_EDGES * C_IN];   // sorted order
__device__ __align__(16) __nv_bfloat16 g_B1[C_MID * KTOT];   // [256][384] = [Whi|Whi|Wlo]
__device__ __align__(16) __nv_bfloat16 g_B3[C_OUT * KTOT];   // [128][384]
__device__ __align__(16) __nv_bfloat16 g_B2v[C_OUT * 3 * C_MID]; // [128][768] = [Whi|Whi|Wlo]
__device__ __align__(16) __nv_bfloat16 g_zhi[(size_t)V_PAD * C_MID];
__device__ __align__(16) __nv_bfloat16 g_zlo[(size_t)V_PAD * C_MID];
__device__ float g_zvmax[V_PAD * C_MID];
__device__ float g_zvertex[V_SEG * C_OUT];
// counting sort
__device__ unsigned g_count[V_PAD];
__device__ unsigned g_offset[V_PAD];
__device__ unsigned g_bsum[256];
__device__ unsigned g_btop[256];
__device__ int g_order[E_EDGES];   // sorted pos -> original edge
__device__ int g_svid[E_EDGES];    // vid in sorted order (non-decreasing)

// ---------------- helpers ----------------
__device__ __forceinline__ uint32_t smem_to_u32(const void* p) {
    uint32_t a;
    asm("{ .reg .u64 t; cvta.to.shared.u64 t, %1; cvt.u32.u64 %0, t; }" : "=r"(a) : "l"(p));
    return a;
}
#define SWZ(o) ((o) ^ (((o) >> 3) & 0x70))

#define CP_ASYNC16(dst, src) \
    asm volatile("cp.async.cg.shared.global [%0], [%1], 16;" :: "r"(dst), "l"(src))
#define CP_COMMIT() asm volatile("cp.async.commit_group;" ::: "memory")
#define CP_WAIT1()  asm volatile("cp.async.wait_group 1;" ::: "memory")
#define CP_WAIT0()  asm volatile("cp.async.wait_group 0;" ::: "memory")

#define LDSM_X4(r0, r1, r2, r3, addr) \
    asm volatile("ldmatrix.sync.aligned.m8n8.x4.shared.b16 {%0,%1,%2,%3}, [%4];" \
                 : "=r"(r0), "=r"(r1), "=r"(r2), "=r"(r3) : "r"(addr))

#define MMA16816(d, a, b) \
    asm volatile("mma.sync.aligned.m16n8k16.row.col.f32.bf16.bf16.f32 " \
                 "{%0,%1,%2,%3}, {%4,%5,%6,%7}, {%8,%9}, {%0,%1,%2,%3};" \
                 : "+f"((d)[0]), "+f"((d)[1]), "+f"((d)[2]), "+f"((d)[3]) \
                 : "r"((a)[0]), "r"((a)[1]), "r"((a)[2]), "r"((a)[3]), \
                   "r"((b)[0]), "r"((b)[1]))

__device__ __forceinline__ void atomicMaxFloat(float* addr, float value) {
    if (value >= 0.0f) atomicMax(reinterpret_cast<int*>(addr), __float_as_int(value));
    else               atomicMin(reinterpret_cast<unsigned int*>(addr), __float_as_uint(value));
}

// ---------------- mma pieces ----------------
// load one 128-row x 128-byte tile, gmem row stride = stride bytes
__device__ __forceinline__ void load_tile(uint32_t sdst, const char* base, int stride, int tid) {
#pragma unroll
    for (int i = 0; i < 4; i++) {
        int idx = i * 256 + tid;
        int row = idx >> 3, col = (idx & 7) << 4;
        CP_ASYNC16(sdst + SWZ(row * 128 + col), base + (size_t)row * stride + col);
    }
}

__device__ __forceinline__ void compute_stage(uint32_t sA, uint32_t sB,
                                              float acc[2][8][4],
                                              int lane, int warp_m, int warp_n) {
    const int g = lane >> 3, lr = lane & 7;
#pragma unroll
    for (int ks = 0; ks < 4; ks++) {
        uint32_t a[2][4];
#pragma unroll
        for (int mi = 0; mi < 2; mi++) {
            int row = warp_m * 32 + mi * 16 + lr + ((g & 1) << 3);
            int kb  = ks * 32 + ((g >> 1) << 4);
            LDSM_X4(a[mi][0], a[mi][1], a[mi][2], a[mi][3], sA + SWZ(row * 128 + kb));
        }
        uint32_t b[8][2];
#pragma unroll
        for (int nj2 = 0; nj2 < 4; nj2++) {
            int nrow = warp_n * 64 + nj2 * 16 + lr + ((g >> 1) << 3);
            int kb   = ks * 32 + ((g & 1) << 4);
            uint32_t r0, r1, r2, r3;
            LDSM_X4(r0, r1, r2, r3, sB + SWZ(nrow * 128 + kb));
            b[nj2 * 2][0] = r0;     b[nj2 * 2][1] = r1;
            b[nj2 * 2 + 1][0] = r2; b[nj2 * 2 + 1][1] = r3;
        }
#pragma unroll
        for (int mi = 0; mi < 2; mi++)
#pragma unroll
            for (int nj = 0; nj < 8; nj++)
                MMA16816(acc[mi][nj], a[mi], b[nj]);
    }
}

// A resident in smem (4x16KB: hi k0, hi k1, lo k0, lo k1) loaded ONCE;
// B 3-stage pipelined, ONE barrier per chunk. smem 112 KB.
__device__ __forceinline__ void mma_mainloop(const __nv_bfloat16* __restrict__ Bmat,
                                             int arow0, int bcol0,
                                             uint32_t sbase, float acc[2][8][4],
                                             int tid, int lane, int warp_m, int warp_n) {
    const uint32_t sB[3] = {sbase + 65536, sbase + 81920, sbase + 98304};
    const char* xh = (const char*)g_xhi + (size_t)arow0 * 256;
    const char* xl = (const char*)g_xlo + (size_t)arow0 * 256;
    const char* bb = (const char*)Bmat + (size_t)bcol0 * (KTOT * 2);

    // group 0: all of A (64 KB) + B chunk 0 ; group 1: B chunk 1
    const char* asrc[4] = {xh, xh + 128, xl, xl + 128};
#pragma unroll
    for (int t = 0; t < 4; t++)
        load_tile(sbase + t * 16384, asrc[t], 256, tid);
    load_tile(sB[0], bb, 768, tid);
    CP_COMMIT();
    load_tile(sB[1], bb + 128, 768, tid);
    CP_COMMIT();

    const uint32_t sAoff[NCHUNK] = {0, 16384, 32768, 49152, 0, 16384};
#pragma unroll
    for (int c = 0; c < NCHUNK; c++) {
        if (c < NCHUNK - 1) CP_WAIT1(); else CP_WAIT0();
        __syncthreads();
        if (c + 2 < NCHUNK) {
            load_tile(sB[(c + 2) % 3], bb + (c + 2) * 128, 768, tid);
            CP_COMMIT();
        }
        compute_stage(sbase + sAoff[c], sB[c % 3], acc, lane, warp_m, warp_n);
    }
    __syncthreads();   // epilogue reuses smem
}

// ---------------- counting sort ----------------
__global__ void k_zero_count() {
    int i = blockIdx.x * 256 + threadIdx.x;
    if (i < V_PAD) g_count[i] = 0;
}

__global__ void k_hist(const int* __restrict__ vid) {
    int e = blockIdx.x * 256 + threadIdx.x;
    atomicAdd(&g_count[__ldg(&vid[e])], 1u);
}

__global__ void k_scan_part() {   // 196 blocks x 256
    __shared__ unsigned s[256];
    int b = blockIdx.x, t = threadIdx.x, i = b * 256 + t;
    s[t] = (i < V_PAD) ? g_count[i] : 0u;
    __syncthreads();
    for (int o = 128; o > 0; o >>= 1) {
        if (t < o) s[t] += s[t + o];
        __syncthreads();
    }
    if (t == 0) g_bsum[b] = s[0];
}

__global__ void k_scan_top() {    // 1 block x 256
    __shared__ unsigned s[256];
    int t = threadIdx.x;
    unsigned v = (t < 196) ? g_bsum[t] : 0u;
    s[t] = v;
    __syncthreads();
    for (int o = 1; o < 256; o <<= 1) {
        unsigned u = (t >= o) ? s[t - o] : 0u;
        __syncthreads();
        s[t] += u;
        __syncthreads();
    }
    g_btop[t] = s[t] - v;
}

__global__ void k_scan_out() {    // 196 blocks x 256
    __shared__ unsigned s[256];
    int b = blockIdx.x, t = threadIdx.x, i = b * 256 + t;
    unsigned c = (i < V_PAD) ? g_count[i] : 0u;
    s[t] = c;
    __syncthreads();
    for (int o = 1; o < 256; o <<= 1) {
        unsigned u = (t >= o) ? s[t - o] : 0u;
        __syncthreads();
        s[t] += u;
        __syncthreads();
    }
    if (i < V_PAD) g_offset[i] = g_btop[b] + s[t] - c;
}

__global__ void k_scatter(const int* __restrict__ vid) {
    int e = blockIdx.x * 256 + threadIdx.x;
    int v = __ldg(&vid[e]);
    unsigned p = atomicAdd(&g_offset[v], 1u);
    g_order[p] = e;
    g_svid[p] = v;
}

// ---------------- prep ----------------
__global__ void k_prep_w(const float* __restrict__ W1,
                         const float* __restrict__ W2e,
                         const float* __restrict__ W2v) {
    int i = blockIdx.x * 256 + threadIdx.x;
    if (i < C_MID * C_IN) {
        int n = i >> 7, k = i & 127;
        float w = W1[i];
        __nv_bfloat16 hi = __float2bfloat16(w);
        __nv_bfloat16 lo = __float2bfloat16(w - __bfloat162float(hi));
        g_B1[n * KTOT + k] = hi;
        g_B1[n * KTOT + 128 + k] = hi;
        g_B1[n * KTOT + 256 + k] = lo;
    }
    if (i < C_OUT * C_IN) {
        int n = i >> 7, k = i & 127;
        float w = W2e[i];
        __nv_bfloat16 hi = __float2bfloat16(w);
        __nv_bfloat16 lo = __float2bfloat16(w - __bfloat162float(hi));
        g_B3[n * KTOT + k] = hi;
        g_B3[n * KTOT + 128 + k] = hi;
        g_B3[n * KTOT + 256 + k] = lo;
    }
    if (i < C_OUT * C_MID) {   // W2v (128,256) -> g_B2v [128][768]
        int n = i >> 8, k = i & 255;
        float w = W2v[i];
        __nv_bfloat16 hi = __float2bfloat16(w);
        __nv_bfloat16 lo = __float2bfloat16(w - __bfloat162float(hi));
        g_B2v[n * 768 + k] = hi;
        g_B2v[n * 768 + 256 + k] = hi;
        g_B2v[n * 768 + 512 + k] = lo;
    }
}

// gather-split: sorted row p <- original edge order[p]
__global__ void k_split_x(const float* __restrict__ x) {
    size_t i = (size_t)blockIdx.x * 256 + threadIdx.x;   // unit = 4 floats
    int prow = (int)(i >> 5);
    int q = (int)(i & 31);
    int e = __ldg(&g_order[prow]);
    float4 v = __ldg(reinterpret_cast<const float4*>(x + (size_t)e * C_IN) + q);
    ushort4 h, l;
    __nv_bfloat16 hb, lb;
    hb = __float2bfloat16(v.x); lb = __float2bfloat16(v.x - __bfloat162float(hb));
    h.x = *(unsigned short*)&hb; l.x = *(unsigned short*)&lb;
    hb = __float2bfloat16(v.y); lb = __float2bfloat16(v.y - __bfloat162float(hb));
    h.y = *(unsigned short*)&hb; l.y = *(unsigned short*)&lb;
    hb = __float2bfloat16(v.z); lb = __float2bfloat16(v.z - __bfloat162float(hb));
    h.z = *(unsigned short*)&hb; l.z = *(unsigned short*)&lb;
    hb = __float2bfloat16(v.w); lb = __float2bfloat16(v.w - __bfloat162float(hb));
    h.w = *(unsigned short*)&hb; l.w = *(unsigned short*)&lb;
    reinterpret_cast<ushort4*>(g_xhi)[i] = h;
    reinterpret_cast<ushort4*>(g_xlo)[i] = l;
}

// fix -inf -> 0, add deferred b1, split z_vmax to bf16 hi/lo
__global__ void k_split_z(const float* __restrict__ b1) {
    size_t i = (size_t)blockIdx.x * 256 + threadIdx.x;   // unit = 4 floats
    if (i >= (size_t)V_PAD * C_MID / 4) return;
    float4 v = reinterpret_cast<const float4*>(g_zvmax)[i];
    float4 bb = __ldg(reinterpret_cast<const float4*>(b1) + (i & 63));
    v.x = (v.x < -1e38f) ? 0.0f : v.x + bb.x;
    v.y = (v.y < -1e38f) ? 0.0f : v.y + bb.y;
    v.z = (v.z < -1e38f) ? 0.0f : v.z + bb.z;
    v.w = (v.w < -1e38f) ? 0.0f : v.w + bb.w;
    ushort4 h, l;
    __nv_bfloat16 hb, lb;
    hb = __float2bfloat16(v.x); lb = __float2bfloat16(v.x - __bfloat162float(hb));
    h.x = *(unsigned short*)&hb; l.x = *(unsigned short*)&lb;
    hb = __float2bfloat16(v.y); lb = __float2bfloat16(v.y - __bfloat162float(hb));
    h.y = *(unsigned short*)&hb; l.y = *(unsigned short*)&lb;
    hb = __float2bfloat16(v.z); lb = __float2bfloat16(v.z - __bfloat162float(hb));
    h.z = *(unsigned short*)&hb; l.z = *(unsigned short*)&lb;
    hb = __float2bfloat16(v.w); lb = __float2bfloat16(v.w - __bfloat162float(hb));
    h.w = *(unsigned short*)&hb; l.w = *(unsigned short*)&lb;
    reinterpret_cast<ushort4*>(g_zhi)[i] = h;
    reinterpret_cast<ushort4*>(g_zlo)[i] = l;
}

__global__ void k_init_zvmax() {
    int i = blockIdx.x * blockDim.x + threadIdx.x;
    const float NEG_INF = __int_as_float(0xFF800000);
    if (i < (V_PAD * C_MID) / 4)
        reinterpret_cast<float4*>(g_zvmax)[i] = make_float4(NEG_INF, NEG_INF, NEG_INF, NEG_INF);
}

// ---------------- GEMM1: z = xs@W1^T, in-tile run-max, few atomics ----------------
__global__ void __launch_bounds__(256, 2)
k_mma1() {
    extern __shared__ char smem[];
    uint32_t sbase = smem_to_u32(smem);
    __shared__ int s_vid[128];
    const int tid = threadIdx.x, wid = tid >> 5, lane = tid & 31;
    const int warp_m = wid & 3, warp_n = wid >> 2;
    const int arow0 = blockIdx.y * 128, bcol0 = blockIdx.x * 128;

    float acc[2][8][4] = {};
    mma_mainloop(g_B1, arow0, bcol0, sbase, acc, tid, lane, warp_m, warp_n);

    // dump fragments to smem [128 rows][stride 132]
    float* s_acc = reinterpret_cast<float*>(smem);
    const int lr4 = lane >> 2, lc2 = (lane & 3) * 2;
#pragma unroll
    for (int mi = 0; mi < 2; mi++) {
        int r0 = warp_m * 32 + mi * 16 + lr4;
#pragma unroll
        for (int nj = 0; nj < 8; nj++) {
            int col = warp_n * 64 + nj * 8 + lc2;
            s_acc[r0 * 132 + col]           = acc[mi][nj][0];
            s_acc[r0 * 132 + col + 1]       = acc[mi][nj][1];
            s_acc[(r0 + 8) * 132 + col]     = acc[mi][nj][2];
            s_acc[(r0 + 8) * 132 + col + 1] = acc[mi][nj][3];
        }
    }
    if (tid < 128) s_vid[tid] = __ldg(&g_svid[arow0 + tid]);
    __syncthreads();

    // per-column run-max over sorted rows: ~1 atomic per (vertex run, col)
    const int col = tid & 127;
    const int rbeg = (tid >> 7) * 64;
    int vcur = s_vid[rbeg];
    float cur = s_acc[rbeg * 132 + col];
    for (int r = rbeg + 1; r < rbeg + 64; r++) {
        int v = s_vid[r];
        float val = s_acc[r * 132 + col];
        if (v != vcur) {
            atomicMaxFloat(&g_zvmax[(size_t)vcur * C_MID + bcol0 + col], cur);
            vcur = v;
            cur = val;
        } else {
            cur = fmaxf(cur, val);
        }
    }
    atomicMaxFloat(&g_zvmax[(size_t)vcur * C_MID + bcol0 + col], cur);
}

// ---------------- GEMM2 (HMMA): z_vertex = split(z_vmax+b1) @ W2v^T ----------------
__global__ void __launch_bounds__(256, 2)
k_mma2() {
    extern __shared__ char smem[];
    uint32_t sbase = smem_to_u32(smem);
    const int tid = threadIdx.x, wid = tid >> 5, lane = tid & 31;
    const int warp_m = wid & 3, warp_n = wid >> 2;
    const int arow0 = blockIdx.x * 128;

    const uint32_t sA[2] = {sbase, sbase + 16384};
    const uint32_t sB[2] = {sbase + 32768, sbase + 49152};
    const char* zh = (const char*)g_zhi + (size_t)arow0 * 512;
    const char* zl = (const char*)g_zlo + (size_t)arow0 * 512;
    const char* bb = (const char*)g_B2v;

    float acc[2][8][4] = {};
    // chunk c: A = (c<4 || c>=8 ? hi : lo) + (c&3)*128 bytes, row stride 512
    load_tile(sA[0], zh, 512, tid);
    load_tile(sB[0], bb, 1536, tid);
    CP_COMMIT();
#pragma unroll
    for (int c = 0; c < NCHUNK2; c++) {
        if (c < NCHUNK2 - 1) {
            int n = c + 1;
            const char* ab = ((n < 4 || n >= 8) ? zh : zl) + (n & 3) * 128;
            load_tile(sA[n & 1], ab, 512, tid);
            load_tile(sB[n & 1], bb + n * 128, 1536, tid);
            CP_COMMIT();
            CP_WAIT1();
        } else {
            CP_WAIT0();
        }
        __syncthreads();
        compute_stage(sA[c & 1], sB[c & 1], acc, lane, warp_m, warp_n);
        __syncthreads();
    }

    const int lr4 = lane >> 2, lc2 = (lane & 3) * 2;
#pragma unroll
    for (int mi = 0; mi < 2; mi++) {
        int p0 = arow0 + warp_m * 32 + mi * 16 + lr4;
        int p1 = p0 + 8;
#pragma unroll
        for (int nj = 0; nj < 8; nj++) {
            int col = warp_n * 64 + nj * 8 + lc2;
            if (p0 < V_SEG)
                *reinterpret_cast<float2*>(&g_zvertex[(size_t)p0 * C_OUT + col]) =
                    make_float2(acc[mi][nj][0], acc[mi][nj][1]);
            if (p1 < V_SEG)
                *reinterpret_cast<float2*>(&g_zvertex[(size_t)p1 * C_OUT + col]) =
                    make_float2(acc[mi][nj][2], acc[mi][nj][3]);
        }
    }
}

// ---------------- GEMM3: out[order[p]] = xs@W2e^T + z_vertex[svid[p]] ----------------
__global__ void __launch_bounds__(256, 2)
k_mma3(float* __restrict__ out) {
    extern __shared__ char smem[];
    uint32_t sbase = smem_to_u32(smem);
    const int tid = threadIdx.x, wid = tid >> 5, lane = tid & 31;
    const int warp_m = wid & 3, warp_n = wid >> 2;
    const int arow0 = blockIdx.y * 128;

    float acc[2][8][4] = {};
    mma_mainloop(g_B3, arow0, 0, sbase, acc, tid, lane, warp_m, warp_n);

    const int lr4 = lane >> 2, lc2 = (lane & 3) * 2;
#pragma unroll
    for (int mi = 0; mi < 2; mi++) {
        int p0 = arow0 + warp_m * 32 + mi * 16 + lr4;
        int p1 = p0 + 8;
        int v0 = __ldg(&g_svid[p0]);
        int v1 = __ldg(&g_svid[p1]);
        int e0 = __ldg(&g_order[p0]);
        int e1 = __ldg(&g_order[p1]);
        const float* z0 = g_zvertex + (size_t)v0 * C_OUT + warp_n * 64 + lc2;
        const float* z1 = g_zvertex + (size_t)v1 * C_OUT + warp_n * 64 + lc2;
        float* o0 = out + (size_t)e0 * C_OUT + warp_n * 64 + lc2;
        float* o1 = out + (size_t)e1 * C_OUT + warp_n * 64 + lc2;
#pragma unroll
        for (int nj = 0; nj < 8; nj++) {
            float2 za = __ldg(reinterpret_cast<const float2*>(z0 + nj * 8));
            float2 zb = __ldg(reinterpret_cast<const float2*>(z1 + nj * 8));
            *reinterpret_cast<float2*>(o0 + nj * 8) =
                make_float2(acc[mi][nj][0] + za.x, acc[mi][nj][1] + za.y);
            *reinterpret_cast<float2*>(o1 + nj * 8) =
                make_float2(acc[mi][nj][2] + zb.x, acc[mi][nj][3] + zb.y);
        }
    }
}

// ---------------- launch ----------------
static constexpr int SMEM_MMA  = 65536 + 3 * 16384;   // 112 KB: A 64KB + B 3x16KB
static constexpr int SMEM_MMA2 = 65536;               // 64 KB: A 2x16 + B 2x16

extern "C" void kernel_launch(void* const* d_in, const int* in_sizes, int n_in,
                              void* d_out, int out_size) {
    const float* x   = (const float*)d_in[0];
    const int*   vid = (const int*)d_in[1];
    const float* W1  = (const float*)d_in[2];
    const float* b1  = (const float*)d_in[3];
    const float* W2e = (const float*)d_in[4];
    const float* W2v = (const float*)d_in[5];
    float* out = (float*)d_out;

    cudaFuncSetAttribute(k_mma1, cudaFuncAttributeMaxDynamicSharedMemorySize, SMEM_MMA);
    cudaFuncSetAttribute(k_mma2, cudaFuncAttributeMaxDynamicSharedMemorySize, SMEM_MMA2);
    cudaFuncSetAttribute(k_mma3, cudaFuncAttributeMaxDynamicSharedMemorySize, SMEM_MMA);

    k_prep_w<<<128, 256>>>(W1, W2e, W2v);
    k_zero_count<<<(V_PAD + 255) / 256, 256>>>();
    k_hist<<<E_EDGES / 256, 256>>>(vid);
    k_scan_part<<<196, 256>>>();
    k_scan_top<<<1, 256>>>();
    k_scan_out<<<196, 256>>>();
    k_scatter<<<E_EDGES / 256, 256>>>(vid);
    k_split_x<<<(E_EDGES * C_IN / 4) / 256, 256>>>(x);
    k_init_zvmax<<<(V_PAD * C_MID / 4 + 255) / 256, 256>>>();
    k_mma1<<<dim3(2, E_EDGES / 128), 256, SMEM_MMA>>>();
    k_split_z<<<(V_PAD * C_MID / 4 + 255) / 256, 256>>>(b1);
    k_mma2<<<V_PAD / 128, 256, SMEM_MMA2>>>();
    k_mma3<<<dim3(1, E_EDGES / 128), 256, SMEM_MMA>>>(out);
}